// round 14
// baseline (speedup 1.0000x reference)
#include <cuda_runtime.h>
#include <cuda_fp16.h>
#include <stdint.h>

#define NTH 256
#define BSTRIDE 147456               // floats per batch (384*384)
static const float INV_SQRT_D = 0.05103103630798288f;

#define NPAIR 18874368               // 256*384*192
#define TILE_U32 2048                // uint32 per 128x32 fragment tile (8KB)
#define WTILES (36 * TILE_U32)

// fragment-ordered 128x32 operand tiles (fp16)
__device__ uint32_t g_zh[NPAIR];                  // z, offA (A-op hi; B via uint4 trick)
__device__ uint32_t g_Yh[NPAIR];                  // Y = z*(Wq^T Wk), offA hi
__device__ uint32_t g_Vth[NPAIR];                 // V transposed, offB hi
__device__ uint32_t g_Ph[NPAIR];                  // exp(scores), offA hi
__device__ uint32_t g_wqTh[WTILES], g_wqTl[WTILES];  // Wq^T, offA split (tiny gemm)
__device__ uint32_t g_wkTh[WTILES];                  // Wk^T, offB
__device__ uint32_t g_wvh[WTILES];                   // Wv rows, offB
__device__ uint32_t g_Abh[WTILES];                   // A=Wq^T Wk, offB
__device__ float    g_a2[384];                       // Wk^T bq
__device__ float    g_v[98304];                      // z . a2
__device__ float    g_rsp[3 * 98304];                // per-kt row partial sums

__device__ __forceinline__ int offA(int r, int p) {
    return ((p >> 3) << 12) + ((r >> 4) << 9) +
           (((r & 7) * 4 + (p & 3)) << 4) +
           (((p >> 2) & 1) << 3) + (((r >> 3) & 1) << 2);
}
__device__ __forceinline__ int offB(int n, int p) {
    return ((p >> 3) << 12) + ((n >> 3) << 8) +
           (((n & 7) * 4 + (p & 3)) << 3) + (((p >> 2) & 1) << 2);
}

#define MMA(d, a, b) \
    asm volatile("mma.sync.aligned.m16n8k16.row.col.f32.f16.f16.f32 " \
        "{%0,%1,%2,%3},{%4,%5,%6,%7},{%8,%9},{%0,%1,%2,%3};" \
        : "+f"((d)[0]), "+f"((d)[1]), "+f"((d)[2]), "+f"((d)[3]) \
        : "r"((a).x), "r"((a).y), "r"((a).z), "r"((a).w), \
          "r"((b).x), "r"((b).y))

#define CP16(sa, gp) \
    asm volatile("cp.async.cg.shared.global [%0], [%1], 16;" :: "r"(sa), "l"(gp))
#define CP_COMMIT() asm volatile("cp.async.commit_group;" ::: "memory")
#define CP_WAIT1()  asm volatile("cp.async.wait_group 1;" ::: "memory")
#define CP_WAIT0()  asm volatile("cp.async.wait_group 0;" ::: "memory")

__device__ __forceinline__ uint32_t smem_u32(const void* p) {
    uint32_t a;
    asm("{ .reg .u64 t; cvta.to.shared.u64 t, %1; cvt.u32.u64 %0, t; }"
        : "=r"(a) : "l"(p));
    return a;
}

// fp16 split: hi = fp16(x), lo = fp16(x - hi)
__device__ __forceinline__ void splitpack(float x, float y,
                                          uint32_t& hi, uint32_t& lo) {
    __half hx = __float2half_rn(x);
    __half hy = __float2half_rn(y);
    float lx = x - __half2float(hx);
    float ly = y - __half2float(hy);
    __half2 h2 = __halves2half2(hx, hy);
    __half2 l2 = __floats2half2_rn(lx, ly);
    hi = reinterpret_cast<uint32_t&>(h2);
    lo = reinterpret_cast<uint32_t&>(l2);
}
__device__ __forceinline__ uint32_t packh2(float x, float y) {
    __half2 h2 = __floats2half2_rn(x, y);
    return reinterpret_cast<uint32_t&>(h2);
}

// fast e^x on the FMA pipe (poly exp2, rel err ~2e-6)
__device__ __forceinline__ float fast_exp(float x) {
    float y = x * 1.4426950408889634f;
    int ir = __float2int_rn(y);
    float f = (y - (float)ir) * 0.6931471805599453f;
    float p = 1.0f + f * (1.0f + f * (0.5f + f * (0.16666667f +
              f * (0.041666667f + f * 0.0083333333f))));
    return p * __int_as_float((ir + 127) << 23);
}

// ---------------- a2 = Wk^T bq ----------------
__global__ void a2_kernel(const float* __restrict__ Wk,
                          const float* __restrict__ bq) {
    int d = threadIdx.x;
    float s = 0.0f;
    for (int f = 0; f < 384; f++) s += Wk[(size_t)f * 384 + d] * bq[f];
    g_a2[d] = s;
}

// -------- presplit z (tiled, coalesced): offA hi tiles + v = z.a2 --------
__global__ __launch_bounds__(256) void presplit_z(const float* __restrict__ z) {
    __shared__ __align__(16) uint32_t st[2048];   // 8KB staging (hi)
    const int tid = threadIdx.x;
    const int rt = blockIdx.x;                    // 0..767 row tile
    const int rl = tid >> 1;                      // local row 0..127
    const int half = tid & 1;
    const int row = (rt << 7) + rl;
    float vpart = 0.0f;

    for (int kt = 0; kt < 12; kt++) {
        const float* zp = z + (size_t)row * 384 + kt * 32 + half * 16;
        float vbuf[16];
        *(float4*)&vbuf[0]  = *(const float4*)(zp);
        *(float4*)&vbuf[4]  = *(const float4*)(zp + 4);
        *(float4*)&vbuf[8]  = *(const float4*)(zp + 8);
        *(float4*)&vbuf[12] = *(const float4*)(zp + 12);

        const float* ap = g_a2 + kt * 32 + half * 16;
        float abuf[16];
        *(float4*)&abuf[0]  = *(const float4*)(ap);
        *(float4*)&abuf[4]  = *(const float4*)(ap + 4);
        *(float4*)&abuf[8]  = *(const float4*)(ap + 8);
        *(float4*)&abuf[12] = *(const float4*)(ap + 12);
#pragma unroll
        for (int c = 0; c < 16; c++) vpart += vbuf[c] * abuf[c];

#pragma unroll
        for (int p = 0; p < 8; p++) {
            int pp = half * 8 + p;
            st[offA(rl, pp) >> 2] = packh2(vbuf[2 * p], vbuf[2 * p + 1]);
        }
        __syncthreads();

        size_t tb = (size_t)(rt * 12 + kt) * TILE_U32;
        int o = tid * 4;
        *(uint4*)&g_zh[tb + o]        = *(uint4*)&st[o];
        *(uint4*)&g_zh[tb + 1024 + o] = *(uint4*)&st[1024 + o];
        __syncthreads();
    }
    vpart += __shfl_xor_sync(0xffffffffu, vpart, 1);
    if (half == 0) g_v[row] = vpart;
}

// -------- presplit weights: WqT split (A), WkT hi (B), Wv hi (B) --------
__global__ __launch_bounds__(256) void presplit_weights(
    const float* __restrict__ Wq, const float* __restrict__ Wk,
    const float* __restrict__ Wv)
{
    const int which = blockIdx.y;
    const int idx = blockIdx.x * 256 + threadIdx.x;   // < 73728
    if (which == 0) {
        int d = idx / 192, fp = idx % 192;
        float x = Wq[(size_t)(2 * fp) * 384 + d];
        float y = Wq[(size_t)(2 * fp + 1) * 384 + d];
        uint32_t h, l; splitpack(x, y, h, l);
        size_t o = (size_t)((d >> 7) * 12 + (fp >> 4)) * TILE_U32 +
                   (offA(d & 127, fp & 15) >> 2);
        g_wqTh[o] = h; g_wqTl[o] = l;
    } else if (which == 1) {
        int e = idx / 192, fp = idx % 192;
        float x = Wk[(size_t)(2 * fp) * 384 + e];
        float y = Wk[(size_t)(2 * fp + 1) * 384 + e];
        size_t o = (size_t)((e >> 7) * 12 + (fp >> 4)) * TILE_U32 +
                   (offB(e & 127, fp & 15) >> 2);
        g_wkTh[o] = packh2(x, y);
    } else {
        int ng = idx / 192, kp = idx % 192;
        float2 vv = *(const float2*)&Wv[(size_t)ng * 384 + kp * 2];
        size_t o = (size_t)((ng >> 7) * 12 + (kp >> 4)) * TILE_U32 +
                   (offB(ng & 127, kp & 15) >> 2);
        g_wvh[o] = packh2(vv.x, vv.y);
    }
}

// ---------------------------------------------------------------------------
// MODE 0: Y & V projections grid(6,768)        A = z hi, B hi       KC=64
// MODE 1: fused scores+exp grid(6,256)         A = Y hi, B = z hi   KC=64
// MODE 2: out = (P V)/rowsum grid(3,3,256)     A = P hi, B = Vt hi  KC=64
// MODE 3: A = Wq^T Wk grid(3,3)                A = WqT split        KC=32
// ---------------------------------------------------------------------------
template <int MODE>
__global__ __launch_bounds__(NTH, 2) void gemm(
    const float* __restrict__ bias, float* __restrict__ outp)
{
    constexpr bool ALO = (MODE == 3);                   // A has lo term
    constexpr int TPS = ALO ? 1 : 2;                    // fragment tiles / stage
    constexpr int SB  = ALO ? 24576 : 32768;            // stage bytes
    constexpr int BO  = 16384;                          // B region offset

    extern __shared__ __align__(16) char sm[];
    const uint32_t smb = smem_u32(sm);
    const int tid = threadIdx.x;
    const int lane = tid & 31;
    const int wid = tid >> 5;
    const int wm = wid >> 2;
    const int wn = wid & 3;

    const uint32_t *Ah, *Al = nullptr, *Bh;
    int NIT, n0 = 0, m0 = 0, w = 0, mt = 0, b = 0;

    if (MODE == 0) {
        w = blockIdx.x / 3;                 // 0 = Y, 1 = V
        int nt = blockIdx.x % 3;
        n0 = nt * 128;
        Ah = g_zh + (size_t)blockIdx.y * 24576;
        Bh = (w == 0) ? (g_Abh + nt * 12 * TILE_U32)
                      : (g_wvh + nt * 12 * TILE_U32);
        NIT = 6;
    } else if (MODE == 1) {
        const int mtab[6] = {0, 1, 1, 2, 2, 2};
        const int ntab[6] = {0, 0, 1, 0, 1, 2};
        mt = mtab[blockIdx.x];
        int nt = ntab[blockIdx.x];
        b = blockIdx.y;
        m0 = mt * 128; n0 = nt * 128;
        Ah = g_Yh + (size_t)(b * 3 + mt) * 24576;
        Bh = g_zh + (size_t)(b * 3 + nt) * 24576;   // z offA tiles as B
        NIT = 6;
    } else if (MODE == 2) {
        int nt = blockIdx.x; mt = blockIdx.y; b = blockIdx.z;
        m0 = mt * 128; n0 = nt * 128;
        Ah = g_Ph + (size_t)(b * 3 + mt) * 24576;
        Bh = g_Vth + (size_t)(b * 3 + nt) * 24576;
        NIT = (mt + 1) * 2;
    } else {
        int nt = blockIdx.x; mt = blockIdx.y;
        m0 = mt * 128; n0 = nt * 128;
        Ah = g_wqTh + (size_t)mt * 24576;
        Al = g_wqTl + (size_t)mt * 24576;
        Bh = g_wkTh + (size_t)nt * 24576;
        NIT = 12;
    }

    auto issue = [&](int it, int st) {
        const uint32_t d0 = smb + st * SB + tid * 16;
        const int go = it * (TPS * TILE_U32) + tid * 4;
        CP16(d0,        Ah + go);  CP16(d0 + 4096,      Ah + go + 1024);
        if (TPS == 2) {
            CP16(d0 + 8192,  Ah + go + 2048);
            CP16(d0 + 12288, Ah + go + 3072);
        }
        if (ALO) {
            CP16(d0 + 8192,  Al + go);
            CP16(d0 + 12288, Al + go + 1024);
        }
        CP16(d0 + BO,   Bh + go);  CP16(d0 + BO + 4096, Bh + go + 1024);
        if (TPS == 2) {
            CP16(d0 + BO + 8192,  Bh + go + 2048);
            CP16(d0 + BO + 12288, Bh + go + 3072);
        }
    };

    issue(0, 0); CP_COMMIT();
    issue(1, 1); CP_COMMIT();

    float acc[4][4][4];
#pragma unroll
    for (int i = 0; i < 4; i++)
#pragma unroll
        for (int j = 0; j < 4; j++)
#pragma unroll
            for (int r = 0; r < 4; r++) acc[i][j][r] = 0.0f;

    int cs = 0, is = 2;
    for (int it = 0; it < NIT; it++) {
        CP_WAIT1();
        __syncthreads();
        if (it + 2 < NIT) issue(it + 2, is);
        CP_COMMIT();

        const char* base = sm + cs * SB;
#pragma unroll
        for (int t = 0; t < TPS; t++) {
#pragma unroll
            for (int s = 0; s < 2; s++) {
                const int toff = t * 8192 + s * 4096;
                uint4 ah[4], al[4];
#pragma unroll
                for (int i = 0; i < 4; i++) {
                    int off = toff + (wm * 4 + i) * 512 + lane * 16;
                    ah[i] = *(const uint4*)(base + off);
                    if (ALO) al[i] = *(const uint4*)(base + 8192 + off);
                }
                if (MODE == 1) {
                    // B tiles are offA layout: one uint4 = two B fragments
#pragma unroll
                    for (int jj = 0; jj < 2; jj++) {
                        int off = BO + toff + (wn * 2 + jj) * 512 + lane * 16;
                        uint4 bhv = *(const uint4*)(base + off);
                        uint2 bh0 = make_uint2(bhv.x, bhv.z);
                        uint2 bh1 = make_uint2(bhv.y, bhv.w);
                        const int j0 = jj * 2, j1 = jj * 2 + 1;
#pragma unroll
                        for (int i = 0; i < 4; i++) MMA(acc[i][j0], ah[i], bh0);
#pragma unroll
                        for (int i = 0; i < 4; i++) MMA(acc[i][j1], ah[i], bh1);
                    }
                } else {
#pragma unroll
                    for (int j = 0; j < 4; j++) {
                        int off = BO + toff + (wn * 4 + j) * 256 + lane * 8;
                        uint2 bh = *(const uint2*)(base + off);
#pragma unroll
                        for (int i = 0; i < 4; i++) MMA(acc[i][j], ah[i], bh);
                        if (ALO) {
#pragma unroll
                            for (int i = 0; i < 4; i++) MMA(acc[i][j], al[i], bh);
                        }
                    }
                }
            }
        }
        cs = (cs == 2) ? 0 : cs + 1;
        is = (is == 2) ? 0 : is + 1;
    }

    // ---- epilogues ----
    const int g = lane >> 2, t = lane & 3;

    if (MODE == 0 && w == 0) {
        // Y: stage hi fragment tile in smem, coalesced write
        CP_WAIT0();
        __syncthreads();
        uint32_t* sp = (uint32_t*)sm;   // hi 32KB
#pragma unroll
        for (int i = 0; i < 4; i++) {
            const int rl = wm * 64 + i * 16 + g;
#pragma unroll
            for (int j = 0; j < 4; j++) {
                const int c0 = n0 + wn * 32 + j * 8 + t * 2;
                uint32_t h0 = packh2(acc[i][j][0], acc[i][j][1]);
                uint32_t h1 = packh2(acc[i][j][2], acc[i][j][3]);
                int kp = (c0 - n0) >> 1;
                int sub = kp >> 4, kpp = kp & 15;
                sp[(sub * 8192 + offA(rl, kpp)) >> 2] = h0;
                sp[(sub * 8192 + offA(rl + 8, kpp)) >> 2] = h1;
            }
        }
        __syncthreads();
        size_t gb = ((size_t)blockIdx.y * 12 + (n0 >> 5)) * TILE_U32;
#pragma unroll
        for (int s4 = 0; s4 < 4; s4++) {
#pragma unroll
            for (int it = 0; it < 2; it++) {
                int o = it * 1024 + tid * 4;
                *(uint4*)&g_Yh[gb + s4 * 2048 + o] = *(const uint4*)&sp[s4 * 2048 + o];
            }
        }
    } else if (MODE == 0) {
        // V: fp32 transpose staging, then hi fragment staging + coalesced
        CP_WAIT0();
        __syncthreads();
        float* s = (float*)sm;   // [128][132]
#pragma unroll
        for (int i = 0; i < 4; i++) {
            const int rl = wm * 64 + i * 16 + g;
#pragma unroll
            for (int j = 0; j < 4; j++) {
                const int c = wn * 32 + j * 8 + t * 2;
                float b0 = bias[n0 + c], b1 = bias[n0 + c + 1];
                s[rl * 132 + c]           = acc[i][j][0] + b0;
                s[rl * 132 + c + 1]       = acc[i][j][1] + b1;
                s[(rl + 8) * 132 + c]     = acc[i][j][2] + b0;
                s[(rl + 8) * 132 + c + 1] = acc[i][j][3] + b1;
            }
        }
        __syncthreads();
        uint32_t* fh = (uint32_t*)(sm + 69632);   // 8KB
        const int bb = blockIdx.y / 3;
        const int l0tok = (blockIdx.y % 3) * 128;
        const int dl = tid & 127;
        const int pb = (tid >> 7) * 8;
#pragma unroll
        for (int sub = 0; sub < 4; sub++) {
            int tb = sub * 32;
#pragma unroll
            for (int pp = 0; pp < 8; pp++) {
                int p = pb + pp;
                float x = s[(tb + 2 * p) * 132 + dl];
                float y = s[(tb + 2 * p + 1) * 132 + dl];
                fh[offB(dl, p) >> 2] = packh2(x, y);
            }
            __syncthreads();
            int tok0 = l0tok + tb;
            size_t tile = (size_t)((bb * 3 + (n0 >> 7)) * 12 + (tok0 >> 5)) * TILE_U32;
            int o = tid * 4;
            *(uint4*)&g_Vth[tile + o]        = *(const uint4*)&fh[o];
            *(uint4*)&g_Vth[tile + 1024 + o] = *(const uint4*)&fh[1024 + o];
            __syncthreads();
        }
    } else if (MODE == 1) {
        // fused: mask + exp (unnormalized) + rowsums + coalesced hi P tiles
        CP_WAIT0();
        __syncthreads();
        uint32_t* sp = (uint32_t*)sm;           // staging: hi 32KB
        float* rs4 = (float*)(sm + 32768);      // [4][128]
        float* vsm = (float*)(sm + 34816);      // [128]
        if (tid < 128) vsm[tid] = g_v[(size_t)b * 384 + n0 + tid];
        __syncthreads();

        float rsum[4][2];
#pragma unroll
        for (int i = 0; i < 4; i++) { rsum[i][0] = 0.0f; rsum[i][1] = 0.0f; }

#pragma unroll
        for (int i = 0; i < 4; i++) {
            const int rl = wm * 64 + i * 16 + g;
            const int q0 = m0 + rl, q1 = q0 + 8;
#pragma unroll
            for (int j = 0; j < 4; j++) {
                const int c0 = n0 + wn * 32 + j * 8 + t * 2;
                const int cl = c0 - n0;
                float vk0 = vsm[cl], vk1 = vsm[cl + 1];
                float p0 = (c0     <= q0) ? fast_exp((acc[i][j][0] + vk0) * INV_SQRT_D) : 0.0f;
                float p1 = (c0 + 1 <= q0) ? fast_exp((acc[i][j][1] + vk1) * INV_SQRT_D) : 0.0f;
                float p2 = (c0     <= q1) ? fast_exp((acc[i][j][2] + vk0) * INV_SQRT_D) : 0.0f;
                float p3 = (c0 + 1 <= q1) ? fast_exp((acc[i][j][3] + vk1) * INV_SQRT_D) : 0.0f;
                rsum[i][0] += p0 + p1;
                rsum[i][1] += p2 + p3;
                int kp = cl >> 1;
                int sub = kp >> 4, kpp = kp & 15;
                sp[(sub * 8192 + offA(rl, kpp)) >> 2]     = packh2(p0, p1);
                sp[(sub * 8192 + offA(rl + 8, kpp)) >> 2] = packh2(p2, p3);
            }
        }
#pragma unroll
        for (int i = 0; i < 4; i++) {
#pragma unroll
            for (int h = 0; h < 2; h++) {
                rsum[i][h] += __shfl_xor_sync(0xffffffffu, rsum[i][h], 1);
                rsum[i][h] += __shfl_xor_sync(0xffffffffu, rsum[i][h], 2);
            }
        }
        if (t == 0) {
#pragma unroll
            for (int i = 0; i < 4; i++) {
                int rl = wm * 64 + i * 16 + g;
                rs4[wn * 128 + rl]     = rsum[i][0];
                rs4[wn * 128 + rl + 8] = rsum[i][1];
            }
        }
        __syncthreads();
        size_t gbase = ((size_t)(b * 3 + mt) * 12 + (n0 >> 5)) * TILE_U32;
#pragma unroll
        for (int s4 = 0; s4 < 4; s4++) {
            size_t tb = gbase + s4 * TILE_U32;
#pragma unroll
            for (int it = 0; it < 2; it++) {
                int o = it * 1024 + tid * 4;
                *(uint4*)&g_Ph[tb + o] = *(const uint4*)&sp[s4 * 2048 + o];
            }
        }
        if (tid < 128) {
            float ssum = rs4[tid] + rs4[128 + tid] + rs4[256 + tid] + rs4[384 + tid];
            g_rsp[(size_t)(n0 >> 7) * 98304 + (size_t)b * 384 + m0 + tid] = ssum;
        }
    } else if (MODE == 2) {
        float* Oo = outp + (size_t)b * BSTRIDE;
#pragma unroll
        for (int i = 0; i < 4; i++) {
            const int r0 = m0 + wm * 64 + i * 16 + g;
            float s0 = 0.0f, s1 = 0.0f;
            for (int k = 0; k <= mt; k++) {
                s0 += g_rsp[(size_t)k * 98304 + (size_t)b * 384 + r0];
                s1 += g_rsp[(size_t)k * 98304 + (size_t)b * 384 + r0 + 8];
            }
            float inv0 = 1.0f / s0, inv1 = 1.0f / s1;
#pragma unroll
            for (int j = 0; j < 4; j++) {
                const int c0 = n0 + wn * 32 + j * 8 + t * 2;
                *(float2*)&Oo[(size_t)r0 * 384 + c0] =
                    make_float2(acc[i][j][0] * inv0, acc[i][j][1] * inv0);
                *(float2*)&Oo[(size_t)(r0 + 8) * 384 + c0] =
                    make_float2(acc[i][j][2] * inv1, acc[i][j][3] * inv1);
            }
        }
    } else {
        // MODE 3: A[d,e] -> transpose-write g_Abh as offB (hi only; tiny)
        CP_WAIT0();
        __syncthreads();
        float* s = (float*)sm;   // [128 d][132 e]
#pragma unroll
        for (int i = 0; i < 4; i++) {
            const int rl = wm * 64 + i * 16 + g;
#pragma unroll
            for (int j = 0; j < 4; j++) {
                const int c = wn * 32 + j * 8 + t * 2;
                s[rl * 132 + c]           = acc[i][j][0];
                s[rl * 132 + c + 1]       = acc[i][j][1];
                s[(rl + 8) * 132 + c]     = acc[i][j][2];
                s[(rl + 8) * 132 + c + 1] = acc[i][j][3];
            }
        }
        __syncthreads();
#pragma unroll
        for (int it = 0; it < 8; it++) {
            int idx = it * 256 + tid;
            int el = idx & 127;
            int db = (idx >> 7) * 8;
            float v[8];
#pragma unroll
            for (int u = 0; u < 8; u++) v[u] = s[(db + u) * 132 + el];
            int k0 = m0 + db;
            size_t tile = (size_t)((n0 >> 7) * 12 + (k0 >> 5)) * TILE_U32;
            int p0 = (k0 & 31) >> 1;
#pragma unroll
            for (int pp = 0; pp < 4; pp++) {
                size_t o = tile + (offB(el, p0 + pp) >> 2);
                g_Abh[o] = packh2(v[2 * pp], v[2 * pp + 1]);
            }
        }
    }
}

// ---------------------------------------------------------------------------
extern "C" void kernel_launch(void* const* d_in, const int* in_sizes, int n_in,
                              void* d_out, int out_size)
{
    const float* z  = (const float*)d_in[0];
    const float* Wq = (const float*)d_in[1];
    const float* bq = (const float*)d_in[2];
    const float* Wk = (const float*)d_in[3];
    const float* Wv = (const float*)d_in[5];
    const float* bv = (const float*)d_in[6];
    float* out = (float*)d_out;

    const int SM0 = 98304;   // 3*32768 loop; V epi needs 77824
    const int SM1 = 98304;
    const int SM2 = 98304;
    const int SM3 = 73728;   // 3*24576 loop; epi 67.6KB

    cudaFuncSetAttribute(gemm<0>, cudaFuncAttributeMaxDynamicSharedMemorySize, SM0);
    cudaFuncSetAttribute(gemm<1>, cudaFuncAttributeMaxDynamicSharedMemorySize, SM1);
    cudaFuncSetAttribute(gemm<2>, cudaFuncAttributeMaxDynamicSharedMemorySize, SM2);
    cudaFuncSetAttribute(gemm<3>, cudaFuncAttributeMaxDynamicSharedMemorySize, SM3);

    dim3 blk(NTH);

    a2_kernel<<<1, 384>>>(Wk, bq);
    presplit_z<<<768, blk>>>(z);
    presplit_weights<<<dim3(288, 3), blk>>>(Wq, Wk, Wv);

    // A = Wq^T Wk (tiny, 2-term for accuracy)
    gemm<3><<<dim3(3, 3), blk, SM3>>>(nullptr, nullptr);

    // Y = z A (offA hi) and V = z Wv^T + bv (offB hi, transposed)
    gemm<0><<<dim3(6, 768), blk, SM0>>>(bv, nullptr);

    // fused scores + exp -> P hi tiles + rowsum partials (lower triangle only)
    gemm<1><<<dim3(6, 256), blk, SM1>>>(nullptr, nullptr);

    // out = (P V) / rowsum
    gemm<2><<<dim3(3, 3, 256), blk, SM2>>>(nullptr, out);
}

// round 15
// speedup vs baseline: 1.0002x; 1.0002x over previous
#include <cuda_runtime.h>
#include <cuda_fp16.h>
#include <stdint.h>

#define NTH 256
#define BSTRIDE 147456               // floats per batch (384*384)
static const float INV_SQRT_D = 0.05103103630798288f;

#define NPAIR 18874368               // 256*384*192
#define TILE_U32 2048                // uint32 per 128x32 fragment tile (8KB)
#define WTILES (36 * TILE_U32)

// fragment-ordered 128x32 operand tiles (fp16), ALL in offA layout
__device__ uint32_t g_zh[NPAIR];                  // z
__device__ uint32_t g_Yh[NPAIR];                  // Y = z*(Wq^T Wk)
__device__ uint32_t g_Vth[NPAIR];                 // V transposed [d rows][tok k]
__device__ uint32_t g_Ph[NPAIR];                  // exp(scores)
__device__ uint32_t g_wqTh[WTILES], g_wqTl[WTILES];  // Wq^T (split, tiny gemm)
__device__ uint32_t g_wkTh[WTILES];                  // Wk^T
__device__ uint32_t g_wvh[WTILES];                   // Wv rows
__device__ uint32_t g_Abh[WTILES];                   // A=Wq^T Wk [e rows][d k]
__device__ float    g_a2[384];                       // Wk^T bq
__device__ float    g_v[98304];                      // z . a2
__device__ float    g_rsp[3 * 98304];                // per-kt row partial sums

__device__ __forceinline__ int offA(int r, int p) {
    return ((p >> 3) << 12) + ((r >> 4) << 9) +
           (((r & 7) * 4 + (p & 3)) << 4) +
           (((p >> 2) & 1) << 3) + (((r >> 3) & 1) << 2);
}

#define MMA(d, a, b) \
    asm volatile("mma.sync.aligned.m16n8k16.row.col.f32.f16.f16.f32 " \
        "{%0,%1,%2,%3},{%4,%5,%6,%7},{%8,%9},{%0,%1,%2,%3};" \
        : "+f"((d)[0]), "+f"((d)[1]), "+f"((d)[2]), "+f"((d)[3]) \
        : "r"((a).x), "r"((a).y), "r"((a).z), "r"((a).w), \
          "r"((b).x), "r"((b).y))

#define CP16(sa, gp) \
    asm volatile("cp.async.cg.shared.global [%0], [%1], 16;" :: "r"(sa), "l"(gp))
#define CP_COMMIT() asm volatile("cp.async.commit_group;" ::: "memory")
#define CP_WAIT2()  asm volatile("cp.async.wait_group 2;" ::: "memory")
#define CP_WAIT0()  asm volatile("cp.async.wait_group 0;" ::: "memory")

__device__ __forceinline__ uint32_t smem_u32(const void* p) {
    uint32_t a;
    asm("{ .reg .u64 t; cvta.to.shared.u64 t, %1; cvt.u32.u64 %0, t; }"
        : "=r"(a) : "l"(p));
    return a;
}

__device__ __forceinline__ void splitpack(float x, float y,
                                          uint32_t& hi, uint32_t& lo) {
    __half hx = __float2half_rn(x);
    __half hy = __float2half_rn(y);
    float lx = x - __half2float(hx);
    float ly = y - __half2float(hy);
    __half2 h2 = __halves2half2(hx, hy);
    __half2 l2 = __floats2half2_rn(lx, ly);
    hi = reinterpret_cast<uint32_t&>(h2);
    lo = reinterpret_cast<uint32_t&>(l2);
}
__device__ __forceinline__ uint32_t packh2(float x, float y) {
    __half2 h2 = __floats2half2_rn(x, y);
    return reinterpret_cast<uint32_t&>(h2);
}

// fast e^x on the FMA pipe (poly exp2, rel err ~2e-6)
__device__ __forceinline__ float fast_exp(float x) {
    float y = x * 1.4426950408889634f;
    int ir = __float2int_rn(y);
    float f = (y - (float)ir) * 0.6931471805599453f;
    float p = 1.0f + f * (1.0f + f * (0.5f + f * (0.16666667f +
              f * (0.041666667f + f * 0.0083333333f))));
    return p * __int_as_float((ir + 127) << 23);
}

// -------- presplit weights (all offA) + a2 = Wk^T bq --------
__global__ __launch_bounds__(256) void presplit_weights(
    const float* __restrict__ Wq, const float* __restrict__ Wk,
    const float* __restrict__ Wv, const float* __restrict__ bq)
{
    const int which = blockIdx.y;
    const int idx = blockIdx.x * 256 + threadIdx.x;   // < 73728
    if (which == 0) {
        int d = idx / 192, fp = idx % 192;
        float x = Wq[(size_t)(2 * fp) * 384 + d];
        float y = Wq[(size_t)(2 * fp + 1) * 384 + d];
        uint32_t h, l; splitpack(x, y, h, l);
        size_t o = (size_t)((d >> 7) * 12 + (fp >> 4)) * TILE_U32 +
                   (offA(d & 127, fp & 15) >> 2);
        g_wqTh[o] = h; g_wqTl[o] = l;
    } else if (which == 1) {
        int e = idx / 192, fp = idx % 192;
        float x = Wk[(size_t)(2 * fp) * 384 + e];
        float y = Wk[(size_t)(2 * fp + 1) * 384 + e];
        size_t o = (size_t)((e >> 7) * 12 + (fp >> 4)) * TILE_U32 +
                   (offA(e & 127, fp & 15) >> 2);
        g_wkTh[o] = packh2(x, y);
    } else if (which == 2) {
        int ng = idx / 192, kp = idx % 192;
        float2 vv = *(const float2*)&Wv[(size_t)ng * 384 + kp * 2];
        size_t o = (size_t)((ng >> 7) * 12 + (kp >> 4)) * TILE_U32 +
                   (offA(ng & 127, kp & 15) >> 2);
        g_wvh[o] = packh2(vv.x, vv.y);
    } else {
        if (idx < 384) {
            float s = 0.0f;
            for (int f = 0; f < 384; f++) s += Wk[(size_t)f * 384 + idx] * bq[f];
            g_a2[idx] = s;
        }
    }
}

// -------- presplit z (tiled, coalesced): offA hi tiles + v = z.a2 --------
__global__ __launch_bounds__(256) void presplit_z(const float* __restrict__ z) {
    __shared__ __align__(16) uint32_t st[2048];   // 8KB staging
    const int tid = threadIdx.x;
    const int rt = blockIdx.x;                    // 0..767 row tile
    const int rl = tid >> 1;                      // local row 0..127
    const int half = tid & 1;
    const int row = (rt << 7) + rl;
    float vpart = 0.0f;

    for (int kt = 0; kt < 12; kt++) {
        const float* zp = z + (size_t)row * 384 + kt * 32 + half * 16;
        float vbuf[16];
        *(float4*)&vbuf[0]  = *(const float4*)(zp);
        *(float4*)&vbuf[4]  = *(const float4*)(zp + 4);
        *(float4*)&vbuf[8]  = *(const float4*)(zp + 8);
        *(float4*)&vbuf[12] = *(const float4*)(zp + 12);

        const float* ap = g_a2 + kt * 32 + half * 16;
        float abuf[16];
        *(float4*)&abuf[0]  = *(const float4*)(ap);
        *(float4*)&abuf[4]  = *(const float4*)(ap + 4);
        *(float4*)&abuf[8]  = *(const float4*)(ap + 8);
        *(float4*)&abuf[12] = *(const float4*)(ap + 12);
#pragma unroll
        for (int c = 0; c < 16; c++) vpart += vbuf[c] * abuf[c];

#pragma unroll
        for (int p = 0; p < 8; p++) {
            int pp = half * 8 + p;
            st[offA(rl, pp) >> 2] = packh2(vbuf[2 * p], vbuf[2 * p + 1]);
        }
        __syncthreads();

        size_t tb = (size_t)(rt * 12 + kt) * TILE_U32;
        int o = tid * 4;
        *(uint4*)&g_zh[tb + o]        = *(uint4*)&st[o];
        *(uint4*)&g_zh[tb + 1024 + o] = *(uint4*)&st[1024 + o];
        __syncthreads();
    }
    vpart += __shfl_xor_sync(0xffffffffu, vpart, 1);
    if (half == 0) g_v[row] = vpart;
}

// ---------------------------------------------------------------------------
// All operands offA; B consumed via uint4 two-fragment extraction.
// MODE 0: Y & V projections grid(6,768)        A = z, B = Ab/Wv
// MODE 1: fused scores+exp grid(6,256)         A = Y, B = z
// MODE 2: out = (P V)/rowsum grid(3,3,256)     A = P, B = Vt
// MODE 3: A = Wq^T Wk grid(3,3)                A = WqT split, B = WkT
// ---------------------------------------------------------------------------
template <int MODE>
__global__ __launch_bounds__(NTH, 2) void gemm(
    const float* __restrict__ bias, float* __restrict__ outp)
{
    constexpr bool ALO = (MODE == 3);                   // A has lo term
    constexpr int SB  = ALO ? 24576 : 16384;            // stage bytes
    constexpr int BO  = ALO ? 16384 : 8192;             // B region offset

    extern __shared__ __align__(16) char sm[];
    const uint32_t smb = smem_u32(sm);
    const int tid = threadIdx.x;
    const int lane = tid & 31;
    const int wid = tid >> 5;
    const int wm = wid >> 2;
    const int wn = wid & 3;

    const uint32_t *Ah, *Al = nullptr, *Bh;
    int NKT, n0 = 0, m0 = 0, w = 0, mt = 0, b = 0;

    if (MODE == 0) {
        w = blockIdx.x / 3;                 // 0 = Y, 1 = V
        int nt = blockIdx.x % 3;
        n0 = nt * 128;
        Ah = g_zh + (size_t)blockIdx.y * 24576;
        Bh = (w == 0) ? (g_Abh + nt * 12 * TILE_U32)
                      : (g_wvh + nt * 12 * TILE_U32);
        NKT = 12;
    } else if (MODE == 1) {
        const int mtab[6] = {0, 1, 1, 2, 2, 2};
        const int ntab[6] = {0, 0, 1, 0, 1, 2};
        mt = mtab[blockIdx.x];
        int nt = ntab[blockIdx.x];
        b = blockIdx.y;
        m0 = mt * 128; n0 = nt * 128;
        Ah = g_Yh + (size_t)(b * 3 + mt) * 24576;
        Bh = g_zh + (size_t)(b * 3 + nt) * 24576;
        NKT = 12;
    } else if (MODE == 2) {
        int nt = blockIdx.x; mt = blockIdx.y; b = blockIdx.z;
        m0 = mt * 128; n0 = nt * 128;
        Ah = g_Ph + (size_t)(b * 3 + mt) * 24576;
        Bh = g_Vth + (size_t)(b * 3 + nt) * 24576;
        NKT = (mt + 1) * 4;
    } else {
        int nt = blockIdx.x; mt = blockIdx.y;
        m0 = mt * 128; n0 = nt * 128;
        Ah = g_wqTh + (size_t)mt * 24576;
        Al = g_wqTl + (size_t)mt * 24576;
        Bh = g_wkTh + (size_t)nt * 24576;
        NKT = 12;
    }

    auto issue = [&](int kt, int st) {
        const uint32_t d0 = smb + st * SB + tid * 16;
        const int go = kt * TILE_U32 + tid * 4;
        CP16(d0,        Ah + go);  CP16(d0 + 4096,      Ah + go + 1024);
        if (ALO) { CP16(d0 + 8192, Al + go); CP16(d0 + 12288, Al + go + 1024); }
        CP16(d0 + BO,   Bh + go);  CP16(d0 + BO + 4096, Bh + go + 1024);
    };

    issue(0, 0); CP_COMMIT();
    issue(1, 1); CP_COMMIT();
    issue(2, 2); CP_COMMIT();

    float acc[4][4][4];
#pragma unroll
    for (int i = 0; i < 4; i++)
#pragma unroll
        for (int j = 0; j < 4; j++)
#pragma unroll
            for (int r = 0; r < 4; r++) acc[i][j][r] = 0.0f;

    int cs = 0, is = 3;
    for (int kt = 0; kt < NKT; kt++) {
        CP_WAIT2();
        __syncthreads();
        if (kt + 3 < NKT) issue(kt + 3, is);
        CP_COMMIT();

        const char* base = sm + cs * SB;
#pragma unroll
        for (int s = 0; s < 2; s++) {
            uint4 ah[4], al[4];
#pragma unroll
            for (int i = 0; i < 4; i++) {
                int off = s * 4096 + (wm * 4 + i) * 512 + lane * 16;
                ah[i] = *(const uint4*)(base + off);
                if (ALO) al[i] = *(const uint4*)(base + 8192 + off);
            }
            // B tiles are offA layout: one uint4 = two n8k16 B fragments
#pragma unroll
            for (int jj = 0; jj < 2; jj++) {
                int off = BO + s * 4096 + (wn * 2 + jj) * 512 + lane * 16;
                uint4 bhv = *(const uint4*)(base + off);
                uint2 bh0 = make_uint2(bhv.x, bhv.z);
                uint2 bh1 = make_uint2(bhv.y, bhv.w);
                const int j0 = jj * 2, j1 = jj * 2 + 1;
#pragma unroll
                for (int i = 0; i < 4; i++) MMA(acc[i][j0], ah[i], bh0);
#pragma unroll
                for (int i = 0; i < 4; i++) MMA(acc[i][j1], ah[i], bh1);
                if (ALO) {
#pragma unroll
                    for (int i = 0; i < 4; i++) MMA(acc[i][j0], al[i], bh0);
#pragma unroll
                    for (int i = 0; i < 4; i++) MMA(acc[i][j1], al[i], bh1);
                }
            }
        }
        cs = (cs == 3) ? 0 : cs + 1;
        is = (is == 3) ? 0 : is + 1;
    }

    // ---- epilogues (fragment j -> column offset j*8; mapping unchanged) ----
    const int g = lane >> 2, t = lane & 3;

    if (MODE == 0 && w == 0) {
        // Y: stage hi fragment tile in smem, coalesced write
        CP_WAIT0();
        __syncthreads();
        uint32_t* sp = (uint32_t*)sm;   // 32KB
#pragma unroll
        for (int i = 0; i < 4; i++) {
            const int rl = wm * 64 + i * 16 + g;
#pragma unroll
            for (int j = 0; j < 4; j++) {
                const int c0 = n0 + wn * 32 + j * 8 + t * 2;
                uint32_t h0 = packh2(acc[i][j][0], acc[i][j][1]);
                uint32_t h1 = packh2(acc[i][j][2], acc[i][j][3]);
                int kp = (c0 - n0) >> 1;
                int sub = kp >> 4, kpp = kp & 15;
                sp[(sub * 8192 + offA(rl, kpp)) >> 2] = h0;
                sp[(sub * 8192 + offA(rl + 8, kpp)) >> 2] = h1;
            }
        }
        __syncthreads();
        size_t gb = ((size_t)blockIdx.y * 12 + (n0 >> 5)) * TILE_U32;
#pragma unroll
        for (int s4 = 0; s4 < 4; s4++) {
#pragma unroll
            for (int it = 0; it < 2; it++) {
                int o = it * 1024 + tid * 4;
                *(uint4*)&g_Yh[gb + s4 * 2048 + o] = *(const uint4*)&sp[s4 * 2048 + o];
            }
        }
    } else if (MODE == 0) {
        // V: fp32 transpose staging, then offA fragment staging + coalesced
        CP_WAIT0();
        __syncthreads();
        float* s = (float*)sm;   // [128][132]
#pragma unroll
        for (int i = 0; i < 4; i++) {
            const int rl = wm * 64 + i * 16 + g;
#pragma unroll
            for (int j = 0; j < 4; j++) {
                const int c = wn * 32 + j * 8 + t * 2;
                float b0 = bias[n0 + c], b1 = bias[n0 + c + 1];
                s[rl * 132 + c]           = acc[i][j][0] + b0;
                s[rl * 132 + c + 1]       = acc[i][j][1] + b1;
                s[(rl + 8) * 132 + c]     = acc[i][j][2] + b0;
                s[(rl + 8) * 132 + c + 1] = acc[i][j][3] + b1;
            }
        }
        __syncthreads();
        uint32_t* fh = (uint32_t*)(sm + 69632);   // 8KB
        const int bb = blockIdx.y / 3;
        const int l0tok = (blockIdx.y % 3) * 128;
        const int dl = tid & 127;
        const int pb = (tid >> 7) * 8;
#pragma unroll
        for (int sub = 0; sub < 4; sub++) {
            int tb = sub * 32;
#pragma unroll
            for (int pp = 0; pp < 8; pp++) {
                int p = pb + pp;
                float x = s[(tb + 2 * p) * 132 + dl];
                float y = s[(tb + 2 * p + 1) * 132 + dl];
                fh[offA(dl, p) >> 2] = packh2(x, y);
            }
            __syncthreads();
            int tok0 = l0tok + tb;
            size_t tile = (size_t)((bb * 3 + (n0 >> 7)) * 12 + (tok0 >> 5)) * TILE_U32;
            int o = tid * 4;
            *(uint4*)&g_Vth[tile + o]        = *(const uint4*)&fh[o];
            *(uint4*)&g_Vth[tile + 1024 + o] = *(const uint4*)&fh[1024 + o];
            __syncthreads();
        }
    } else if (MODE == 1) {
        // fused: mask + exp (unnormalized) + rowsums + coalesced hi P tiles
        CP_WAIT0();
        __syncthreads();
        uint32_t* sp = (uint32_t*)sm;           // staging: 32KB
        float* rs4 = (float*)(sm + 32768);      // [4][128]
        float* vsm = (float*)(sm + 34816);      // [128]
        if (tid < 128) vsm[tid] = g_v[(size_t)b * 384 + n0 + tid];
        __syncthreads();

        float rsum[4][2];
#pragma unroll
        for (int i = 0; i < 4; i++) { rsum[i][0] = 0.0f; rsum[i][1] = 0.0f; }

#pragma unroll
        for (int i = 0; i < 4; i++) {
            const int rl = wm * 64 + i * 16 + g;
            const int q0 = m0 + rl, q1 = q0 + 8;
#pragma unroll
            for (int j = 0; j < 4; j++) {
                const int c0 = n0 + wn * 32 + j * 8 + t * 2;
                const int cl = c0 - n0;
                float vk0 = vsm[cl], vk1 = vsm[cl + 1];
                float p0 = (c0     <= q0) ? fast_exp((acc[i][j][0] + vk0) * INV_SQRT_D) : 0.0f;
                float p1 = (c0 + 1 <= q0) ? fast_exp((acc[i][j][1] + vk1) * INV_SQRT_D) : 0.0f;
                float p2 = (c0     <= q1) ? fast_exp((acc[i][j][2] + vk0) * INV_SQRT_D) : 0.0f;
                float p3 = (c0 + 1 <= q1) ? fast_exp((acc[i][j][3] + vk1) * INV_SQRT_D) : 0.0f;
                rsum[i][0] += p0 + p1;
                rsum[i][1] += p2 + p3;
                int kp = cl >> 1;
                int sub = kp >> 4, kpp = kp & 15;
                sp[(sub * 8192 + offA(rl, kpp)) >> 2]     = packh2(p0, p1);
                sp[(sub * 8192 + offA(rl + 8, kpp)) >> 2] = packh2(p2, p3);
            }
        }
#pragma unroll
        for (int i = 0; i < 4; i++) {
#pragma unroll
            for (int h = 0; h < 2; h++) {
                rsum[i][h] += __shfl_xor_sync(0xffffffffu, rsum[i][h], 1);
                rsum[i][h] += __shfl_xor_sync(0xffffffffu, rsum[i][h], 2);
            }
        }
        if (t == 0) {
#pragma unroll
            for (int i = 0; i < 4; i++) {
                int rl = wm * 64 + i * 16 + g;
                rs4[wn * 128 + rl]     = rsum[i][0];
                rs4[wn * 128 + rl + 8] = rsum[i][1];
            }
        }
        __syncthreads();
        size_t gbase = ((size_t)(b * 3 + mt) * 12 + (n0 >> 5)) * TILE_U32;
#pragma unroll
        for (int s4 = 0; s4 < 4; s4++) {
            size_t tb = gbase + s4 * TILE_U32;
#pragma unroll
            for (int it = 0; it < 2; it++) {
                int o = it * 1024 + tid * 4;
                *(uint4*)&g_Ph[tb + o] = *(const uint4*)&sp[s4 * 2048 + o];
            }
        }
        if (tid < 128) {
            float ssum = rs4[tid] + rs4[128 + tid] + rs4[256 + tid] + rs4[384 + tid];
            g_rsp[(size_t)(n0 >> 7) * 98304 + (size_t)b * 384 + m0 + tid] = ssum;
        }
    } else if (MODE == 2) {
        float* Oo = outp + (size_t)b * BSTRIDE;
#pragma unroll
        for (int i = 0; i < 4; i++) {
            const int r0 = m0 + wm * 64 + i * 16 + g;
            float s0 = 0.0f, s1 = 0.0f;
            for (int k = 0; k <= mt; k++) {
                s0 += g_rsp[(size_t)k * 98304 + (size_t)b * 384 + r0];
                s1 += g_rsp[(size_t)k * 98304 + (size_t)b * 384 + r0 + 8];
            }
            float inv0 = 1.0f / s0, inv1 = 1.0f / s1;
#pragma unroll
            for (int j = 0; j < 4; j++) {
                const int c0 = n0 + wn * 32 + j * 8 + t * 2;
                *(float2*)&Oo[(size_t)r0 * 384 + c0] =
                    make_float2(acc[i][j][0] * inv0, acc[i][j][1] * inv0);
                *(float2*)&Oo[(size_t)(r0 + 8) * 384 + c0] =
                    make_float2(acc[i][j][2] * inv1, acc[i][j][3] * inv1);
            }
        }
    } else {
        // MODE 3: A[d,e] -> transpose-write g_Abh as offA [e rows][d k] (tiny)
        CP_WAIT0();
        __syncthreads();
        float* s = (float*)sm;   // [128 d][132 e]
#pragma unroll
        for (int i = 0; i < 4; i++) {
            const int rl = wm * 64 + i * 16 + g;
#pragma unroll
            for (int j = 0; j < 4; j++) {
                const int c = wn * 32 + j * 8 + t * 2;
                s[rl * 132 + c]           = acc[i][j][0];
                s[rl * 132 + c + 1]       = acc[i][j][1];
                s[(rl + 8) * 132 + c]     = acc[i][j][2];
                s[(rl + 8) * 132 + c + 1] = acc[i][j][3];
            }
        }
        __syncthreads();
#pragma unroll
        for (int it = 0; it < 8; it++) {
            int idx = it * 256 + tid;
            int el = idx & 127;
            int db = (idx >> 7) * 8;
            float v[8];
#pragma unroll
            for (int u = 0; u < 8; u++) v[u] = s[(db + u) * 132 + el];
            int k0 = m0 + db;
            size_t tile = (size_t)((n0 >> 7) * 12 + (k0 >> 5)) * TILE_U32;
            int p0 = (k0 & 31) >> 1;
#pragma unroll
            for (int pp = 0; pp < 4; pp++) {
                size_t o = tile + (offA(el, p0 + pp) >> 2);
                g_Abh[o] = packh2(v[2 * pp], v[2 * pp + 1]);
            }
        }
    }
}

// ---------------------------------------------------------------------------
extern "C" void kernel_launch(void* const* d_in, const int* in_sizes, int n_in,
                              void* d_out, int out_size)
{
    const float* z  = (const float*)d_in[0];
    const float* Wq = (const float*)d_in[1];
    const float* bq = (const float*)d_in[2];
    const float* Wk = (const float*)d_in[3];
    const float* Wv = (const float*)d_in[5];
    const float* bv = (const float*)d_in[6];
    float* out = (float*)d_out;

    const int SM0 = 77824;   // 4*16384 loop; V epi needs 77824
    const int SM1 = 65536;   // 4*16384 loop; epi ~35KB
    const int SM2 = 65536;
    const int SM3 = 98304;   // 4*24576 loop; epi 67.6KB

    cudaFuncSetAttribute(gemm<0>, cudaFuncAttributeMaxDynamicSharedMemorySize, SM0);
    cudaFuncSetAttribute(gemm<1>, cudaFuncAttributeMaxDynamicSharedMemorySize, SM1);
    cudaFuncSetAttribute(gemm<2>, cudaFuncAttributeMaxDynamicSharedMemorySize, SM2);
    cudaFuncSetAttribute(gemm<3>, cudaFuncAttributeMaxDynamicSharedMemorySize, SM3);

    dim3 blk(NTH);

    presplit_weights<<<dim3(288, 4), blk>>>(Wq, Wk, Wv, bq);
    presplit_z<<<768, blk>>>(z);

    // A = Wq^T Wk (tiny, 2-term for accuracy)
    gemm<3><<<dim3(3, 3), blk, SM3>>>(nullptr, nullptr);

    // Y = z A (offA) and V = z Wv^T + bv (offA, transposed)
    gemm<0><<<dim3(6, 768), blk, SM0>>>(bv, nullptr);

    // fused scores + exp -> P tiles + rowsum partials (lower triangle only)
    gemm<1><<<dim3(6, 256), blk, SM1>>>(nullptr, nullptr);

    // out = (P V) / rowsum
    gemm<2><<<dim3(3, 3, 256), blk, SM2>>>(nullptr, out);
}